// round 4
// baseline (speedup 1.0000x reference)
#include <cuda_runtime.h>
#include <cuda_bf16.h>
#include <cstdint>

// Problem constants
#define N_U   1024
#define BATCH 4096
#define H     10
#define INV1023 (1.0f / 1023.0f)

// ---------------------------------------------------------------------------
// Scratch (device globals)
// ---------------------------------------------------------------------------
__device__ float g_colpart[32][N_U];
__device__ float g_colsum[N_U];
__device__ float g_rowsum[N_U];
__device__ float g_F[N_U][H];
__device__ float g_G[N_U][H];
__device__ float g_ACR[3][H];
__device__ __align__(256) float g_NW[N_U * N_U];                 // new_weight [k][n]

// Split operands (bf16 as ushort), deduped: A hi used by segs 0 & 1.
__device__ __align__(256) unsigned short g_Ahi[BATCH * N_U];     // 8 MB
__device__ __align__(256) unsigned short g_Alo[BATCH * N_U];     // 8 MB
__device__ __align__(256) unsigned short g_Bhi[N_U * N_U];       // 2 MB  [n][k]
__device__ __align__(256) unsigned short g_Blo[N_U * N_U];       // 2 MB  [n][k]

// ---------------------------------------------------------------------------
// Helpers
// ---------------------------------------------------------------------------
__device__ __forceinline__ uint32_t smem_u32(const void* p) {
    uint32_t a;
    asm("{ .reg .u64 t; cvta.to.shared.u64 t, %1; cvt.u32.u64 %0, t; }" : "=r"(a) : "l"(p));
    return a;
}
__device__ __forceinline__ unsigned short bf16u(float x) {
    return __bfloat16_as_ushort(__float2bfloat16_rn(x));
}
__device__ __forceinline__ float bf16f(float x) {
    return __bfloat162float(__float2bfloat16_rn(x));
}

#define CP_ASYNC16(dst, src) \
    asm volatile("cp.async.cg.shared.global [%0], [%1], 16;" :: "r"(dst), "l"(src))
#define CP_COMMIT() asm volatile("cp.async.commit_group;")
#define CP_WAIT(n)  asm volatile("cp.async.wait_group %0;" :: "n"(n))

#define LDMATRIX_X4(r0, r1, r2, r3, addr) \
    asm volatile("ldmatrix.sync.aligned.m8n8.x4.shared.b16 {%0,%1,%2,%3}, [%4];" \
        : "=r"(r0), "=r"(r1), "=r"(r2), "=r"(r3) : "r"(addr))

#define MMA_BF16(c0, c1, c2, c3, a0, a1, a2, a3, b0, b1) \
    asm volatile("mma.sync.aligned.m16n8k16.row.col.f32.bf16.bf16.f32 " \
        "{%0,%1,%2,%3}, {%4,%5,%6,%7}, {%8,%9}, {%0,%1,%2,%3};" \
        : "+f"(c0), "+f"(c1), "+f"(c2), "+f"(c3) \
        : "r"(a0), "r"(a1), "r"(a2), "r"(a3), "r"(b0), "r"(b1))

// ---------------------------------------------------------------------------
// Column sums (deterministic two-stage)
// ---------------------------------------------------------------------------
__global__ void __launch_bounds__(128) colpart_kernel(const float* __restrict__ W) {
    int col = blockIdx.x * 128 + threadIdx.x;
    int r0  = blockIdx.y * 32;
    float s = 0.f;
#pragma unroll
    for (int r = 0; r < 32; r++) s += W[(r0 + r) * N_U + col];
    g_colpart[blockIdx.y][col] = s;
}
__global__ void __launch_bounds__(256) colsum_kernel() {
    int col = blockIdx.x * 256 + threadIdx.x;
    float s = 0.f;
#pragma unroll
    for (int b = 0; b < 32; b++) s += g_colpart[b][col];
    g_colsum[col] = s;
}

// ---------------------------------------------------------------------------
// Row sums
// ---------------------------------------------------------------------------
__global__ void __launch_bounds__(256) rowsum_kernel(const float* __restrict__ W) {
    __shared__ float red[8];
    int row = blockIdx.x, tid = threadIdx.x;
    float4 v = *(const float4*)(W + row * N_U + tid * 4);
    float s = v.x + v.y + v.z + v.w;
#pragma unroll
    for (int o = 16; o > 0; o >>= 1) s += __shfl_xor_sync(0xffffffffu, s, o);
    if ((tid & 31) == 0) red[tid >> 5] = s;
    __syncthreads();
    if (tid == 0) {
        float t = 0.f;
#pragma unroll
        for (int i = 0; i < 8; i++) t += red[i];
        g_rowsum[row] = t;
    }
}

// ---------------------------------------------------------------------------
// Precompute F (per-i,h), G (per-j,h), coefficient tables — fully parallel.
// ---------------------------------------------------------------------------
__global__ void __launch_bounds__(256) precompute_kernel(const float* __restrict__ W1,
                                                         const float* __restrict__ b1) {
    int idx = blockIdx.x * 256 + threadIdx.x;
    if (idx < N_U * H) {
        int i = idx / H, h = idx % H;
        float acc = 0.f;
#pragma unroll
        for (int t = 0; t < 10; t++) {
            float coef = W1[(3 + t) * H + h] + W1[(43 + t) * H + h]
                       - W1[(23 + t) * H + h] * INV1023;
            if ((i >> (9 - t)) & 1) acc += coef;
        }
        g_F[i][h] = acc;
    } else if (idx < 2 * N_U * H) {
        int r = idx - N_U * H;
        int j = r / H, h = r % H;
        float acc = b1[h];
#pragma unroll
        for (int s = 0; s < 10; s++) {
            float coef = W1[(13 + s) * H + h] + W1[(33 + s) * H + h]
                       - W1[(53 + s) * H + h] * INV1023;
            if ((j >> (9 - s)) & 1) acc += coef;
            acc += (512.f * INV1023) * (W1[(23 + s) * H + h] + W1[(53 + s) * H + h]);
        }
        g_G[j][h] = acc;
    } else if (idx < 2 * N_U * H + H) {
        int h = idx - 2 * N_U * H;
        g_ACR[0][h] = W1[h] - (W1[H + h] + W1[2 * H + h]) * INV1023;
        g_ACR[1][h] = W1[H + h] * INV1023;
        g_ACR[2][h] = W1[2 * H + h] * INV1023;
    }
}

// ---------------------------------------------------------------------------
// Per-cell MLP -> g_NW
// ---------------------------------------------------------------------------
__global__ void __launch_bounds__(256) mlp_kernel(const float* __restrict__ W,
                                                  const float* __restrict__ W2,
                                                  const float* __restrict__ b2,
                                                  const float* __restrict__ W3,
                                                  const float* __restrict__ b3) {
    __shared__ float sW2[H * H], sB2[H], sW3[H], sF[H];
    __shared__ float sA[H], sC[H], sR[H];
    __shared__ float sb3;
    int tid = threadIdx.x, i = blockIdx.x;
    if (tid < H * H) sW2[tid] = W2[tid];
    if (tid < H) {
        sB2[tid] = b2[tid];
        sW3[tid] = W3[tid * 21];
        sF[tid]  = g_F[i][tid];
        sA[tid]  = g_ACR[0][tid];
        sC[tid]  = g_ACR[1][tid];
        sR[tid]  = g_ACR[2][tid];
    }
    if (tid == 0) sb3 = b3[0];
    __syncthreads();

    float rs = g_rowsum[i];
#pragma unroll
    for (int c = 0; c < 4; c++) {
        int j = c * 256 + tid;
        float w  = W[i * N_U + j];
        float cs = g_colsum[j];
        float z[H];
#pragma unroll
        for (int h = 0; h < H; h++) {
            float v = fmaf(sA[h], w, fmaf(sC[h], cs, fmaf(sR[h], rs, sF[h] + g_G[j][h])));
            z[h] = fmaxf(v, 0.f);
        }
        float upd = sb3;
#pragma unroll
        for (int k = 0; k < H; k++) {
            float y = sB2[k];
#pragma unroll
            for (int h = 0; h < H; h++) y = fmaf(z[h], sW2[h * H + k], y);
            upd = fmaf(fmaxf(y, 0.f), sW3[k], upd);
        }
        g_NW[i * N_U + j] = w + upd;
    }
}

// ---------------------------------------------------------------------------
// Transpose + split NW -> g_Bhi/g_Blo [n][k]
// ---------------------------------------------------------------------------
__global__ void __launch_bounds__(256) transpose_split_kernel() {
    __shared__ float tile[32][33];
    int bx = blockIdx.x, by = blockIdx.y;
    int tx = threadIdx.x, ty = threadIdx.y;           // 32 x 8
    int i0 = by * 32, j0 = bx * 32;
#pragma unroll
    for (int r = 0; r < 4; r++)
        tile[ty * 4 + r][tx] = g_NW[(i0 + ty * 4 + r) * N_U + j0 + tx];
    __syncthreads();
#pragma unroll
    for (int r = 0; r < 4; r++) {
        int j = j0 + ty * 4 + r;
        int i = i0 + tx;
        float v  = tile[tx][ty * 4 + r];
        float hi = bf16f(v);
        g_Bhi[j * N_U + i] = bf16u(v);
        g_Blo[j * N_U + i] = bf16u(v - hi);
    }
}

// ---------------------------------------------------------------------------
// Split X -> g_Ahi/g_Alo [m][k]
// ---------------------------------------------------------------------------
__global__ void __launch_bounds__(256) split_x_kernel(const float* __restrict__ X) {
    int gid = blockIdx.x * 256 + threadIdx.x;
    int idx = gid * 4;
    float4 v = *(const float4*)(X + idx);
    uint32_t hi01 = (uint32_t)bf16u(v.x) | ((uint32_t)bf16u(v.y) << 16);
    uint32_t hi23 = (uint32_t)bf16u(v.z) | ((uint32_t)bf16u(v.w) << 16);
    uint32_t lo01 = (uint32_t)bf16u(v.x - bf16f(v.x)) | ((uint32_t)bf16u(v.y - bf16f(v.y)) << 16);
    uint32_t lo23 = (uint32_t)bf16u(v.z - bf16f(v.z)) | ((uint32_t)bf16u(v.w - bf16f(v.w)) << 16);
    *(uint2*)(g_Ahi + idx) = make_uint2(hi01, hi23);
    *(uint2*)(g_Alo + idx) = make_uint2(lo01, lo23);
}

// ---------------------------------------------------------------------------
// GEMM: out = relu( sum of 3 split passes ), bf16 mma.sync.
// BM=128, BN=256, BK=32, 256 threads (8 warps, 2m x 4n), warp tile 64x64.
// 4-stage cp.async pipeline; padded smem rows (40 bf16 = 80B) conflict-free.
// Segments: 0: Ahi*Bhi  1: Ahi*Blo  2: Alo*Bhi   (each 1024 K => 96 BK-iters)
// ---------------------------------------------------------------------------
#define BM 128
#define BN 256
#define BK 32
#define STAGES 4
#define AROW 40
#define ABYTES (BM * AROW * 2)           // 10240
#define BBYTES (BN * AROW * 2)           // 20480
#define STBYTES (ABYTES + BBYTES)        // 30720
#define SMEM_GEMM (STAGES * STBYTES)     // 122880

__global__ void __launch_bounds__(256, 1) gemm_mma_kernel(float* __restrict__ out) {
    extern __shared__ char smem[];
    uint32_t sb = smem_u32(smem);
    int tid  = threadIdx.x;
    int wid  = tid >> 5;
    int lane = tid & 31;

    int mt = blockIdx.x & 31;            // 32 m-tiles
    int nt = blockIdx.x >> 5;            // 4 n-tiles
    int mw = wid & 1;                    // warp m (2)
    int nw = wid >> 1;                   // warp n (4)

    const unsigned short* Aseg[3];
    const unsigned short* Bseg[3];
    Aseg[0] = g_Ahi + (size_t)(mt * BM) * N_U;
    Aseg[1] = Aseg[0];
    Aseg[2] = g_Alo + (size_t)(mt * BM) * N_U;
    Bseg[0] = g_Bhi + (size_t)(nt * BN) * N_U;
    Bseg[1] = g_Blo + (size_t)(nt * BN) * N_U;
    Bseg[2] = Bseg[0];

    float c[4][8][4];
#pragma unroll
    for (int f = 0; f < 4; f++)
#pragma unroll
        for (int n = 0; n < 8; n++)
#pragma unroll
            for (int q = 0; q < 4; q++) c[f][n][q] = 0.f;

    const int ITERS = 96;

    auto load_stage = [&](int it, int st) {
        int seg = it >> 5;
        int k0  = (it & 31) * BK;
        uint32_t abase = sb + st * STBYTES;
        uint32_t bbase = abase + ABYTES;
        const unsigned short* Ag = Aseg[seg];
        const unsigned short* Bg = Bseg[seg];
        // A: 512 16B chunks, 2 per thread
#pragma unroll
        for (int q = 0; q < 2; q++) {
            int cchunk = tid + q * 256;
            int row = cchunk >> 2;
            int off = (cchunk & 3) * 8;
            CP_ASYNC16(abase + row * (AROW * 2) + off * 2,
                       (const char*)(Ag + (size_t)row * N_U + k0 + off));
        }
        // B: 1024 chunks, 4 per thread
#pragma unroll
        for (int q = 0; q < 4; q++) {
            int cchunk = tid + q * 256;
            int row = cchunk >> 2;
            int off = (cchunk & 3) * 8;
            CP_ASYNC16(bbase + row * (AROW * 2) + off * 2,
                       (const char*)(Bg + (size_t)row * N_U + k0 + off));
        }
    };

#pragma unroll
    for (int s = 0; s < STAGES - 1; s++) {
        load_stage(s, s);
        CP_COMMIT();
    }

    int lrow = lane & 15;
    int lcol = (lane >> 4) * 16;

    for (int i = 0; i < ITERS; i++) {
        CP_WAIT(2);
        __syncthreads();

        int nx = i + STAGES - 1;
        if (nx < ITERS) load_stage(nx, nx & (STAGES - 1));
        CP_COMMIT();

        int st = i & (STAGES - 1);
        uint32_t abase = sb + st * STBYTES;
        uint32_t bbase = abase + ABYTES;

#pragma unroll
        for (int ks = 0; ks < 2; ks++) {
            uint32_t a[4][4];
#pragma unroll
            for (int f = 0; f < 4; f++)
                LDMATRIX_X4(a[f][0], a[f][1], a[f][2], a[f][3],
                    abase + (mw * 64 + f * 16 + lrow) * (AROW * 2) + ks * 32 + lcol);
            uint32_t b[8][2];
#pragma unroll
            for (int g = 0; g < 4; g++) {
                uint32_t r0, r1, r2, r3;
                LDMATRIX_X4(r0, r1, r2, r3,
                    bbase + (nw * 64 + g * 16 + lrow) * (AROW * 2) + ks * 32 + lcol);
                b[2 * g][0] = r0;  b[2 * g][1] = r2;
                b[2 * g + 1][0] = r1;  b[2 * g + 1][1] = r3;
            }
#pragma unroll
            for (int f = 0; f < 4; f++)
#pragma unroll
                for (int n = 0; n < 8; n++)
                    MMA_BF16(c[f][n][0], c[f][n][1], c[f][n][2], c[f][n][3],
                             a[f][0], a[f][1], a[f][2], a[f][3], b[n][0], b[n][1]);
        }
        __syncthreads();
    }

    // Epilogue: relu + store
    int rbase = mt * BM + mw * 64 + (lane >> 2);
    int cbase = nt * BN + nw * 64 + (lane & 3) * 2;
#pragma unroll
    for (int f = 0; f < 4; f++) {
#pragma unroll
        for (int n = 0; n < 8; n++) {
            int r = rbase + f * 16;
            int cc = cbase + n * 8;
            float2 v0, v1;
            v0.x = fmaxf(c[f][n][0], 0.f);
            v0.y = fmaxf(c[f][n][1], 0.f);
            v1.x = fmaxf(c[f][n][2], 0.f);
            v1.y = fmaxf(c[f][n][3], 0.f);
            *(float2*)(out + (size_t)r * N_U + cc)       = v0;
            *(float2*)(out + (size_t)(r + 8) * N_U + cc) = v1;
        }
    }
}

// ---------------------------------------------------------------------------
// Row softmax in-place
// ---------------------------------------------------------------------------
__global__ void __launch_bounds__(256) softmax_kernel(float* __restrict__ out) {
    __shared__ float redm[8];
    __shared__ float reds[8];
    __shared__ float bval[2];
    int row = blockIdx.x, tid = threadIdx.x;
    int lane = tid & 31, wid = tid >> 5;

    float4 v = *(float4*)(out + row * N_U + tid * 4);
    float m = fmaxf(fmaxf(v.x, v.y), fmaxf(v.z, v.w));
#pragma unroll
    for (int o = 16; o > 0; o >>= 1) m = fmaxf(m, __shfl_xor_sync(0xffffffffu, m, o));
    if (lane == 0) redm[wid] = m;
    __syncthreads();
    if (tid == 0) {
        float t = redm[0];
#pragma unroll
        for (int i = 1; i < 8; i++) t = fmaxf(t, redm[i]);
        bval[0] = t;
    }
    __syncthreads();
    m = bval[0];
    v.x = expf(v.x - m); v.y = expf(v.y - m);
    v.z = expf(v.z - m); v.w = expf(v.w - m);
    float s = v.x + v.y + v.z + v.w;
#pragma unroll
    for (int o = 16; o > 0; o >>= 1) s += __shfl_xor_sync(0xffffffffu, s, o);
    if (lane == 0) reds[wid] = s;
    __syncthreads();
    if (tid == 0) {
        float t = 0.f;
#pragma unroll
        for (int i = 0; i < 8; i++) t += reds[i];
        bval[1] = 1.f / t;
    }
    __syncthreads();
    float inv = bval[1];
    v.x *= inv; v.y *= inv; v.z *= inv; v.w *= inv;
    *(float4*)(out + row * N_U + tid * 4) = v;
}

// ---------------------------------------------------------------------------
// Entry point
// ---------------------------------------------------------------------------
extern "C" void kernel_launch(void* const* d_in, const int* in_sizes, int n_in,
                              void* d_out, int out_size) {
    const float* X      = (const float*)d_in[0];
    const float* weight = (const float*)d_in[1];
    const float* W1     = (const float*)d_in[3];
    const float* b1     = (const float*)d_in[4];
    const float* W2     = (const float*)d_in[5];
    const float* b2     = (const float*)d_in[6];
    const float* W3     = (const float*)d_in[7];
    const float* b3     = (const float*)d_in[8];
    float* out = (float*)d_out;

    static bool attr_done = false;
    if (!attr_done) {
        cudaFuncSetAttribute(gemm_mma_kernel,
                             cudaFuncAttributeMaxDynamicSharedMemorySize, SMEM_GEMM);
        attr_done = true;
    }

    split_x_kernel<<<BATCH * N_U / 1024, 256>>>(X);
    colpart_kernel<<<dim3(8, 32), 128>>>(weight);
    colsum_kernel<<<4, 256>>>();
    rowsum_kernel<<<N_U, 256>>>(weight);
    precompute_kernel<<<(2 * N_U * H + H + 255) / 256, 256>>>(W1, b1);
    mlp_kernel<<<N_U, 256>>>(weight, W2, b2, W3, b3);
    transpose_split_kernel<<<dim3(32, 32), dim3(32, 8)>>>();
    gemm_mma_kernel<<<128, 256, SMEM_GEMM>>>(out);
    softmax_kernel<<<BATCH, 256>>>(out);
}